// round 16
// baseline (speedup 1.0000x reference)
#include <cuda_runtime.h>

#define DD 1024
#define NN 512
#define RR 513
#define TPB 256
#define KMAX 128
#define CKMAX 513

// padded index for inverse-FFT smem buffer (float2 units)
#define PIDX(i) ((i) + ((i) >> 4))
// per-life pads for forward scratch (float units; +2 steps keep float2 alignment)
#define FDX(P, i) ((P) == 1 ? (i) + 2 * ((i) >> 5) : \
                   (P) == 2 ? (i) + 2 * ((i) >> 6) : (i))

#define BSTRIDE 1092

// Twiddle table: g_tw[k] = (cos, -sin)(2*pi*k/1024), k=0..512, double-rounded to float.
__device__ float2 g_tw[RR];

__global__ void tw_init_kernel() {
    int i = blockIdx.x * blockDim.x + threadIdx.x;
    if (i < RR) {
        double a = (double)i / (double)NN;
        g_tw[i] = make_float2((float)cospi(a), (float)(-sinpi(a)));
    }
}

__device__ __forceinline__ float xla_hypot(float re, float im) {
    float a = fabsf(re), b = fabsf(im);
    float mx = fmaxf(a, b), mn = fminf(a, b);
    if (mx == 0.f) return 0.f;
    float div = __fdiv_rn(mn, mx);
    float t = __fadd_rn(1.f, __fmul_rn(div, div));
    return __fmul_rn(mx, __fsqrt_rn(t));
}

__device__ __forceinline__ float2 cmulc(float2 z, float2 w) {
    return make_float2(fmaf(z.x, w.x,  z.y * w.y),
                       fmaf(z.y, w.x, -z.x * w.y));
}

// ---- bit-exact radf4 butterfly helpers ----
__device__ __forceinline__ float4 r4_real(float c0, float c1, float c2, float c3) {
    float tr1 = c3 + c1, tr2 = c0 + c2;
    return make_float4(tr2 + tr1, c0 - c2, c3 - c1, tr2 - tr1);
}
__device__ __forceinline__ float4 r4_tail(float c0, float a, float cv, float b) {
    const float HS = 0.70710678118654752440f;
    float ti1 = __fmul_rn(-HS, __fadd_rn(a, b));
    float tr1 = __fmul_rn( HS, __fsub_rn(a, b));
    return make_float4(c0 + tr1, ti1 - cv, c0 - tr1, ti1 + cv);
}
struct R4C { float2 o0, o1, o2, o3; };
__device__ __forceinline__ R4C r4_cplx(float2 c0v, float2 cv1, float2 cv2, float2 cv3,
                                       float2 t1, float2 t2, float2 t3) {
    float w1r = t1.x, w1i = -t1.y;
    float w2r = t2.x, w2i = -t2.y;
    float w3r = t3.x, w3i = -t3.y;
    float cr2 = __fadd_rn(__fmul_rn(w1r, cv1.x), __fmul_rn(w1i, cv1.y));
    float ci2 = __fsub_rn(__fmul_rn(w1r, cv1.y), __fmul_rn(w1i, cv1.x));
    float cr3 = __fadd_rn(__fmul_rn(w2r, cv2.x), __fmul_rn(w2i, cv2.y));
    float ci3 = __fsub_rn(__fmul_rn(w2r, cv2.y), __fmul_rn(w2i, cv2.x));
    float cr4 = __fadd_rn(__fmul_rn(w3r, cv3.x), __fmul_rn(w3i, cv3.y));
    float ci4 = __fsub_rn(__fmul_rn(w3r, cv3.y), __fmul_rn(w3i, cv3.x));
    float tr1 = cr4 + cr2, tr4 = cr4 - cr2;
    float ti1 = ci2 + ci4, ti4 = ci2 - ci4;
    float tr2 = c0v.x + cr3, tr3 = c0v.x - cr3;
    float ti2 = c0v.y + ci3, ti3 = c0v.y - ci3;
    R4C r;
    r.o0 = make_float2(tr1 + tr2, ti1 + ti2);
    r.o3 = make_float2(tr2 - tr1, ti1 - ti2);
    r.o2 = make_float2(ti4 + tr3, tr4 + ti3);
    r.o1 = make_float2(tr3 - ti4, tr4 - ti3);
    return r;
}

// ---- generic radf4 middle pass (pass 3: B(P1) -> A(P2)) ----
template<int PIN, int POUT>
__device__ __forceinline__ void radf4_pass(
    const float* __restrict__ cc, float* __restrict__ ch,
    const float2* __restrict__ tw, int ido, int l1, int m_step, int t)
{
#define RD1(i)    cc[FDX(PIN, (i) + 1)]
#define RD2(L)    (*(const float2*)&cc[FDX(PIN, (L) + 1)])
#define WR1(i, v) do { ch[FDX(POUT, (i) + 1)] = (v); } while (0)
#define WR2(L, v) do { *(float2*)&ch[FDX(POUT, (L) + 1)] = (v); } while (0)
    if (t < l1) {
        int k = t;
        float4 r = r4_real(RD1(ido * k), RD1(ido * (k + l1)),
                           RD1(ido * (k + 2 * l1)), RD1(ido * (k + 3 * l1)));
        WR1(ido * (4 * k),               r.x);
        WR1((ido - 1) + ido * (1 + 4*k), r.y);
        WR1(ido * (2 + 4 * k),           r.z);
        WR1((ido - 1) + ido * (3 + 4*k), r.w);
    }
    const int nI = (ido >> 1) - 1;
    const int s2 = l1, e2 = l1 + l1 * nI;
    if (t >= s2 && t < e2) {
        int q = t - s2;
        int k = q % l1, ii = q / l1;
        int i = 2 + 2 * ii;
        int ic = ido - i;
        int m1 = (i >> 1) * m_step;
        R4C r = r4_cplx(RD2((i-1) + ido*k),
                        RD2((i-1) + ido*(k + l1)),
                        RD2((i-1) + ido*(k + 2*l1)),
                        RD2((i-1) + ido*(k + 3*l1)),
                        tw[m1], tw[2*m1], tw[3*m1]);
        WR2((i-1)  + ido*(4*k),     r.o0);
        WR2((ic-1) + ido*(3 + 4*k), r.o3);
        WR2((i-1)  + ido*(2 + 4*k), r.o2);
        WR2((ic-1) + ido*(1 + 4*k), r.o1);
    }
    if (t >= e2 && t < e2 + l1) {
        int k = t - e2;
        float4 r = r4_tail(RD1((ido-1) + ido*k), RD1((ido-1) + ido*(k + l1)),
                           RD1((ido-1) + ido*(k + 2*l1)), RD1((ido-1) + ido*(k + 3*l1)));
        WR1((ido-1) + ido*(4*k),     r.x);
        WR1(ido*(1 + 4*k),           r.y);
        WR1((ido-1) + ido*(2 + 4*k), r.z);
        WR1(ido*(3 + 4*k),           r.w);
    }
#undef RD1
#undef RD2
#undef WR1
#undef WR2
}

__global__ __launch_bounds__(TPB, 7) void spectral_kernel(
    const float* __restrict__ x, const float* __restrict__ gains,
    const float* __restrict__ bias, float* __restrict__ y, int kk)
{
    __shared__ __align__(16) float s_pool[3212];
    __shared__ float2 s_tw[RR];
    __shared__ float  s_sc[RR];
    __shared__ float  s_g[KMAX];
    __shared__ int    s_hist[256];
    __shared__ int    s_goff[256];
    __shared__ unsigned long long s_ckey[CKMAX];
    __shared__ int    s_wsumi[8];
    __shared__ float  s_wmax[8];
    __shared__ int    s_cut;

    float* B = s_pool;
    float* A = s_pool + BSTRIDE;
    float* H = s_pool + 2 * BSTRIDE;

    const int t = threadIdx.x;
    const int lane = t & 31;
    const int wrp = t >> 5;
    const long long row = blockIdx.x;
    const float* xrow = x + row * DD;

    // ---- fused pass 1+2 (threads 0..63) overlapped with s_tw/s_g staging ----
    if (t < 64) {
        const int k2 = t;
        float q[4][4];
#pragma unroll
        for (int m = 0; m < 4; ++m) {
            int base = k2 + 64 * m;
            float4 r = r4_real(xrow[base], xrow[base + 256],
                               xrow[base + 512], xrow[base + 768]);
            q[m][0] = r.x; q[m][1] = r.y; q[m][2] = r.z; q[m][3] = r.w;
        }
#define WB1(j, v) B[FDX(1, 16*k2 + (j) + 1)] = (v)
#define WB2(j, v) *(float2*)&B[FDX(1, 16*k2 + (j) + 1)] = (v)
        {   float4 r = r4_real(q[0][0], q[1][0], q[2][0], q[3][0]);
            WB1(0, r.x); WB2(7, make_float2(r.y, r.z)); WB1(15, r.w);
        }
        {   float4 r = r4_tail(q[0][3], q[1][3], q[2][3], q[3][3]);
            WB2(3, make_float2(r.x, r.y)); WB2(11, make_float2(r.z, r.w));
        }
        {   float2 w1 = g_tw[64], w2 = g_tw[128], w3 = g_tw[192];
            R4C r = r4_cplx(make_float2(q[0][1], q[0][2]),
                            make_float2(q[1][1], q[1][2]),
                            make_float2(q[2][1], q[2][2]),
                            make_float2(q[3][1], q[3][2]),
                            w1, w2, w3);
            WB2(1, r.o0); WB2(5, r.o1); WB2(9, r.o2); WB2(13, r.o3);
        }
#undef WB1
#undef WB2
    } else {
        for (int i = t - 64; i < RR; i += 192) s_tw[i] = g_tw[i];
        for (int i = t - 64; i < kk; i += 192) s_g[i] = gains[i];
    }
    __syncthreads();

    // ---- pass 3 : B(P1) -> A(P2), ido=16, l1=16 ----
    radf4_pass<1,2>(B, A, s_tw, 16, 16, 16, t);
    __syncthreads();

    // ---- fused pass 4+5 : A(P2) -> H; idle threads init selection arrays ----
#define RD1A(i) A[FDX(2, (i) + 1)]
#define RD2A(L) (*(const float2*)&A[FDX(2, (L) + 1)])
    if (t < 62) {
        const int p = (t >> 1) + 1;
        const int h = t & 1;
        const int i4 = 2 * p;
        float2 ra[4], rb[4];
        {
            float2 w1 = s_tw[4*p], w2 = s_tw[8*p], w3 = s_tw[12*p];
#pragma unroll
            for (int k4 = 0; k4 < 4; ++k4) {
                R4C r = r4_cplx(RD2A((i4-1) + 64*k4),
                                RD2A((i4-1) + 64*(k4+4)),
                                RD2A((i4-1) + 64*(k4+8)),
                                RD2A((i4-1) + 64*(k4+12)),
                                w1, w2, w3);
                ra[k4] = h ? r.o1 : r.o0;
                rb[k4] = h ? r.o3 : r.o2;
            }
        }
        const int I5a = h ? (128 - i4) : i4;
        const int I5b = h ? (256 - i4) : (i4 + 128);
        float2 wa1 = s_tw[h ? (64 - p)      : p];
        float2 wa2 = s_tw[h ? (128 - 2*p)   : 2*p];
        float2 wa3 = s_tw[h ? (192 - 3*p)   : 3*p];
        float2 wb1 = s_tw[h ? (128 - p)     : (64 + p)];
        float2 wb2 = s_tw[h ? (256 - 2*p)   : (128 + 2*p)];
        float2 wb3 = s_tw[h ? (384 - 3*p)   : (192 + 3*p)];
#define EMIT5(I5, V, W1, W2, W3) do { \
            R4C r = r4_cplx((V)[0], (V)[1], (V)[2], (V)[3], (W1), (W2), (W3)); \
            *(float2*)&H[(I5)]        = r.o0; \
            *(float2*)&H[1024 - (I5)] = r.o3; \
            *(float2*)&H[(I5) + 512]  = r.o2; \
            *(float2*)&H[512 - (I5)]  = r.o1; \
        } while (0)
        EMIT5(I5a, ra, wa1, wa2, wa3);
        EMIT5(I5b, rb, wb1, wb2, wb3);
#undef EMIT5
    } else if (t == 64) {
        float q0[4][4];
#pragma unroll
        for (int k4 = 0; k4 < 4; ++k4) {
            float4 r = r4_real(RD1A(64*k4), RD1A(64*(k4+4)),
                               RD1A(64*(k4+8)), RD1A(64*(k4+12)));
            q0[k4][0] = r.x; q0[k4][1] = r.y; q0[k4][2] = r.z; q0[k4][3] = r.w;
        }
        {   float4 s = r4_real(q0[0][0], q0[1][0], q0[2][0], q0[3][0]);
            H[1] = s.x; H[512] = s.y; H[513] = s.z; H[1024] = s.w; }
        {   R4C r = r4_cplx(make_float2(q0[0][1], q0[0][2]),
                            make_float2(q0[1][1], q0[1][2]),
                            make_float2(q0[2][1], q0[2][2]),
                            make_float2(q0[3][1], q0[3][2]),
                            s_tw[64], s_tw[128], s_tw[192]);
            *(float2*)&H[128] = r.o0; *(float2*)&H[896] = r.o3;
            *(float2*)&H[640] = r.o2; *(float2*)&H[384] = r.o1; }
        {   float4 s = r4_tail(q0[0][3], q0[1][3], q0[2][3], q0[3][3]);
            *(float2*)&H[256] = make_float2(s.x, s.y);
            *(float2*)&H[768] = make_float2(s.z, s.w); }
    } else if (t == 96) {
        float qt[4][4];
#pragma unroll
        for (int k4 = 0; k4 < 4; ++k4) {
            float4 r = r4_tail(RD1A(63 + 64*k4), RD1A(63 + 64*(k4+4)),
                               RD1A(63 + 64*(k4+8)), RD1A(63 + 64*(k4+12)));
            qt[k4][0] = r.x; qt[k4][1] = r.y; qt[k4][2] = r.z; qt[k4][3] = r.w;
        }
        {   R4C r = r4_cplx(make_float2(qt[0][0], qt[0][1]),
                            make_float2(qt[1][0], qt[1][1]),
                            make_float2(qt[2][0], qt[2][1]),
                            make_float2(qt[3][0], qt[3][1]),
                            s_tw[32], s_tw[64], s_tw[96]);
            *(float2*)&H[64]  = r.o0; *(float2*)&H[960] = r.o3;
            *(float2*)&H[576] = r.o2; *(float2*)&H[448] = r.o1; }
        {   R4C r = r4_cplx(make_float2(qt[0][2], qt[0][3]),
                            make_float2(qt[1][2], qt[1][3]),
                            make_float2(qt[2][2], qt[2][3]),
                            make_float2(qt[3][2], qt[3][3]),
                            s_tw[96], s_tw[192], s_tw[288]);
            *(float2*)&H[192] = r.o0; *(float2*)&H[832] = r.o3;
            *(float2*)&H[704] = r.o2; *(float2*)&H[320] = r.o1; }
    } else if (t >= 128) {
        int u = t - 128;
        s_hist[u] = 0; s_goff[u] = 0;
        s_hist[u + 128] = 0; s_goff[u + 128] = 0;
        for (int i = u; i < RR; i += 128) s_sc[i] = 0.f;
    }
#undef RD1A
#undef RD2A
    __syncthreads();
    // H (shift 1): X0 = H[1]; Xk = (H[2k], H[2k+1]) k=1..511; X512 = H[1024]

    // ---- quad-ownership spectrum read: thread t<=128 owns {t, 512-t, 256-t, 256+t} ----
    float2 v0, v1, v2, v3;
    float m0 = 0.f, m1 = 0.f, m2 = 0.f, m3 = 0.f;
    if (t <= 128) {
        const float2* h2 = (const float2*)H;
        v0 = (t == 0) ? make_float2(H[1], 0.f)    : h2[t];
        v1 = (t == 0) ? make_float2(H[1024], 0.f) : h2[512 - t];
        v2 = h2[256 - t];
        v3 = h2[256 + t];
        m0 = xla_hypot(v0.x, v0.y);
        m1 = xla_hypot(v1.x, v1.y);
        m2 = xla_hypot(v2.x, v2.y);
        m3 = xla_hypot(v3.x, v3.y);
    }
    // duplicates (t=0: bin3 dup of bin2; t=128: bins2,3 dup of 0,1) are harmless for max
    float mv = fmaxf(fmaxf(m0, m1), fmaxf(m2, m3));
#pragma unroll
    for (int o = 16; o; o >>= 1) mv = fmaxf(mv, __shfl_xor_sync(0xffffffffu, mv, o));
    if (lane == 0) s_wmax[wrp] = mv;
    __syncthreads();
    if (t == 0) {
        float mz = s_wmax[0];
#pragma unroll
        for (int i2 = 1; i2 < 8; ++i2) mz = fmaxf(mz, s_wmax[i2]);
        s_wmax[0] = mz * 1.0000002f + 1e-30f;
    }
    __syncthreads();

    const float hi = s_wmax[0];
    const float inv = 256.f / hi;
    const int b0 = min((int)(m0 * inv), 255);
    const int b1 = min((int)(m1 * inv), 255);
    const int b2 = min((int)(m2 * inv), 255);
    const int b3 = min((int)(m3 * inv), 255);

    // ---- histogram (guards drop the t=0 / t=128 duplicates) ----
    if (t <= 128) { atomicAdd(&s_hist[b0], 1); atomicAdd(&s_hist[b1], 1); }
    if (t <= 127) atomicAdd(&s_hist[b2], 1);
    if (t >= 1 && t <= 127) atomicAdd(&s_hist[b3], 1);
    __syncthreads();

    // ---- suffix scan ----
    {
        int v = s_hist[t];
#pragma unroll
        for (int d = 1; d < 32; d <<= 1) {
            int tmp = __shfl_down_sync(0xffffffffu, v, d);
            if (lane + d < 32) v += tmp;
        }
        if (lane == 0) s_wsumi[wrp] = v;
        __syncthreads();
        int add = 0;
#pragma unroll
        for (int w = 0; w < 8; ++w) add += (w > wrp) ? s_wsumi[w] : 0;
        v += add;
        s_hist[t] = v;
    }
    __syncthreads();

    // ---- cut bin ----
    {
        int sa = s_hist[t];
        int sb = (t == 255) ? 0 : s_hist[t + 1];
        if (sa >= kk && sb < kk) s_cut = t;
    }
    __syncthreads();
    const int cutb = s_cut;
    const int cnt = s_hist[cutb];

    // ---- compact candidates ----
#define EMITC(bq, mq, fq) do { \
        int gs = ((bq) < 255) ? s_hist[(bq) + 1] : 0; \
        int off = atomicAdd(&s_goff[(bq)], 1); \
        s_ckey[gs + off] = (((unsigned long long)__float_as_uint(mq)) << 10) \
                         | (unsigned long long)(1023 - (fq)); \
    } while (0)
    if (t <= 128 && b0 >= cutb) EMITC(b0, m0, t);
    if (t <= 128 && b1 >= cutb) EMITC(b1, m1, 512 - t);
    if (t <= 127 && b2 >= cutb) EMITC(b2, m2, 256 - t);
    if (t >= 1 && t <= 127 && b3 >= cutb) EMITC(b3, m3, 256 + t);
#undef EMITC
    __syncthreads();

    // ---- exact rank within bin; scatter gains ----
    for (int i = t; i < cnt; i += TPB) {
        unsigned long long ki = s_ckey[i];
        float m = __uint_as_float((unsigned)(ki >> 10));
        int b = min((int)(m * inv), 255);
        int gs = (b < 255) ? s_hist[b + 1] : 0;
        int ge = gs + s_goff[b];
        int r  = gs;
        for (int j = gs; j < ge; ++j) r += (s_ckey[j] > ki) ? 1 : 0;
        if (r < kk) {
            int f = 1023 - (int)(ki & 1023ull);
            s_sc[f] = s_g[r];
        }
    }
    __syncthreads();

    // ---- pack from registers (mirror-pair symmetry) + fused inverse stage 1 ----
    float2* zb = (float2*)s_pool;
    if (t <= 128) {
        const float sc1v = 1.f / 1024.f;
        float a0s = s_sc[t], a1s = s_sc[512 - t];
        float a2s = s_sc[256 - t], a3s = s_sc[256 + t];
        // pair A: k=t, km=512-t  ->  zA0=z(t), zA1=z(512-t)
        float ykx = v0.x * a0s, yky = v0.y * a0s;
        float ymx = v1.x * a1s, ymy = v1.y * a1s;
        float px = ykx + ymx, py = yky - ymy;
        float qx = ykx - ymx, qy = yky + ymy;
        float2 w = s_tw[t];
        float tx = qx * w.x + qy * w.y;
        float ty = qy * w.x - qx * w.y;
        float2 zA0 = make_float2(sc1v * (px - ty), sc1v * (py + tx));
        float2 zA1 = make_float2(sc1v * (px + ty), sc1v * (tx - py));
        // pair B: k=256-t, km=256+t  ->  zB0=z(256-t), zB1=z(256+t)
        ykx = v2.x * a2s; yky = v2.y * a2s;
        ymx = v3.x * a3s; ymy = v3.y * a3s;
        px = ykx + ymx; py = yky - ymy;
        qx = ykx - ymx; qy = yky + ymy;
        w = s_tw[256 - t];
        tx = qx * w.x + qy * w.y;
        ty = qy * w.x - qx * w.y;
        float2 zB0 = make_float2(sc1v * (px - ty), sc1v * (py + tx));
        float2 zB1 = make_float2(sc1v * (px + ty), sc1v * (tx - py));
        // stage-1 pair (t, t+256): u=z(t), v=z(t+256)=zB1  (t=128: zB1==zA1, correct)
        int br = __brev(t) >> 23;
        zb[PIDX(br)]     = make_float2(zA0.x + zB1.x, zA0.y + zB1.y);
        zb[PIDX(br + 1)] = make_float2(zA0.x - zB1.x, zA0.y - zB1.y);
        // stage-1 pair (256-t, 512-t): u=zB0, v=zA1
        if (t >= 1 && t <= 127) {
            int br2 = __brev(256 - t) >> 23;
            zb[PIDX(br2)]     = make_float2(zB0.x + zA1.x, zB0.y + zA1.y);
            zb[PIDX(br2 + 1)] = make_float2(zB0.x - zA1.x, zB0.y - zA1.y);
        }
    }
    __syncthreads();

    // ---- inverse: fused double radix-2 stages (2,3)(4,5)(6,7) ----
#pragma unroll
    for (int lsp = 2; lsp <= 6; lsp += 2) {
        if (t < 128) {
            const int h1 = 1 << (lsp - 1);
            const int low = t & (h1 - 1);
            const int high = t >> (lsp - 1);
            const int bidx = low | (high << (lsp + 1));
            float2 z0 = zb[PIDX(bidx)];
            float2 z1 = zb[PIDX(bidx + h1)];
            float2 z2 = zb[PIDX(bidx + 2 * h1)];
            float2 z3 = zb[PIDX(bidx + 3 * h1)];
            float2 wa = s_tw[low << (10 - lsp)];
            int wbi = low << (9 - lsp);
            float2 wb = s_tw[wbi];
            float2 wc = s_tw[wbi + 256];
            float2 t1 = cmulc(z1, wa);
            float2 a0 = make_float2(z0.x + t1.x, z0.y + t1.y);
            float2 a1 = make_float2(z0.x - t1.x, z0.y - t1.y);
            float2 t2 = cmulc(z3, wa);
            float2 a2 = make_float2(z2.x + t2.x, z2.y + t2.y);
            float2 a3 = make_float2(z2.x - t2.x, z2.y - t2.y);
            float2 u = cmulc(a2, wb);
            float2 v = cmulc(a3, wc);
            zb[PIDX(bidx)]          = make_float2(a0.x + u.x, a0.y + u.y);
            zb[PIDX(bidx + h1)]     = make_float2(a1.x + v.x, a1.y + v.y);
            zb[PIDX(bidx + 2*h1)]   = make_float2(a0.x - u.x, a0.y - u.y);
            zb[PIDX(bidx + 3*h1)]   = make_float2(a1.x - v.x, a1.y - v.y);
        }
        __syncthreads();
    }

    // ---- fused stages 8+9 + bias add + gmem write (threads 0..127, 4 outputs) ----
    if (t < 128) {
        const float2* b2 = (const float2*)bias;
        float2* yr = (float2*)(y + row * DD);
        float2 u0 = zb[PIDX(t)];
        float2 u1 = zb[PIDX(t + 128)];
        float2 u2 = zb[PIDX(t + 256)];
        float2 u3 = zb[PIDX(t + 384)];
        float2 w8 = s_tw[t << 2];
        float2 t1 = cmulc(u1, w8);
        float2 a0 = make_float2(u0.x + t1.x, u0.y + t1.y);
        float2 a1 = make_float2(u0.x - t1.x, u0.y - t1.y);
        float2 t2 = cmulc(u3, w8);
        float2 a2 = make_float2(u2.x + t2.x, u2.y + t2.y);
        float2 a3 = make_float2(u2.x - t2.x, u2.y - t2.y);
        float2 w9a = s_tw[t << 1];
        float2 w9b = s_tw[(t << 1) + 256];
        float2 vv0 = cmulc(a2, w9a);
        float2 vv1 = cmulc(a3, w9b);
        float2 bb0 = b2[t];
        float2 bb1 = b2[t + 128];
        float2 bb2 = b2[t + 256];
        float2 bb3 = b2[t + 384];
        yr[t]       = make_float2(a0.x + vv0.x + bb0.x, a0.y + vv0.y + bb0.y);
        yr[t + 128] = make_float2(a1.x + vv1.x + bb1.x, a1.y + vv1.y + bb1.y);
        yr[t + 256] = make_float2(a0.x - vv0.x + bb2.x, a0.y - vv0.y + bb2.y);
        yr[t + 384] = make_float2(a1.x - vv1.x + bb3.x, a1.y - vv1.y + bb3.y);
    }
}

extern "C" void kernel_launch(void* const* d_in, const int* in_sizes, int n_in,
                              void* d_out, int out_size) {
    const float* x     = (const float*)d_in[0];
    const float* gains = (const float*)d_in[1];
    const float* bias  = (const float*)d_in[2];
    float* y = (float*)d_out;

    int rows = in_sizes[0] / DD;
    int kk = in_sizes[1];
    if (kk > KMAX) kk = KMAX;

    tw_init_kernel<<<3, 256>>>();
    spectral_kernel<<<rows, TPB>>>(x, gains, bias, y, kk);
}

// round 17
// speedup vs baseline: 1.0735x; 1.0735x over previous
#include <cuda_runtime.h>

#define DD 1024
#define NN 512
#define RR 513
#define TPB 256
#define KMAX 128
#define CKMAX 513

// padded index for inverse-FFT smem buffer (float2 units)
#define PIDX(i) ((i) + ((i) >> 4))
// per-life pads for forward scratch (float units; +2 steps keep float2 alignment)
#define FDX(P, i) ((P) == 1 ? (i) + 2 * ((i) >> 5) : \
                   (P) == 2 ? (i) + 2 * ((i) >> 6) : (i))

#define BSTRIDE 1092

// Twiddle table: g_tw[k] = (cos, -sin)(2*pi*k/1024), k=0..512, double-rounded to float.
__device__ float2 g_tw[RR];

__global__ void tw_init_kernel() {
    int i = blockIdx.x * blockDim.x + threadIdx.x;
    if (i < RR) {
        double a = (double)i / (double)NN;
        g_tw[i] = make_float2((float)cospi(a), (float)(-sinpi(a)));
    }
}

__device__ __forceinline__ float xla_hypot(float re, float im) {
    float a = fabsf(re), b = fabsf(im);
    float mx = fmaxf(a, b), mn = fminf(a, b);
    if (mx == 0.f) return 0.f;
    float div = __fdiv_rn(mn, mx);
    float t = __fadd_rn(1.f, __fmul_rn(div, div));
    return __fmul_rn(mx, __fsqrt_rn(t));
}

__device__ __forceinline__ float2 cmulc(float2 z, float2 w) {
    return make_float2(fmaf(z.x, w.x,  z.y * w.y),
                       fmaf(z.y, w.x, -z.x * w.y));
}

// ---- bit-exact radf4 butterfly helpers ----
__device__ __forceinline__ float4 r4_real(float c0, float c1, float c2, float c3) {
    float tr1 = c3 + c1, tr2 = c0 + c2;
    return make_float4(tr2 + tr1, c0 - c2, c3 - c1, tr2 - tr1);
}
__device__ __forceinline__ float4 r4_tail(float c0, float a, float cv, float b) {
    const float HS = 0.70710678118654752440f;
    float ti1 = __fmul_rn(-HS, __fadd_rn(a, b));
    float tr1 = __fmul_rn( HS, __fsub_rn(a, b));
    return make_float4(c0 + tr1, ti1 - cv, c0 - tr1, ti1 + cv);
}
struct R4C { float2 o0, o1, o2, o3; };
__device__ __forceinline__ R4C r4_cplx(float2 c0v, float2 cv1, float2 cv2, float2 cv3,
                                       float2 t1, float2 t2, float2 t3) {
    float w1r = t1.x, w1i = -t1.y;
    float w2r = t2.x, w2i = -t2.y;
    float w3r = t3.x, w3i = -t3.y;
    float cr2 = __fadd_rn(__fmul_rn(w1r, cv1.x), __fmul_rn(w1i, cv1.y));
    float ci2 = __fsub_rn(__fmul_rn(w1r, cv1.y), __fmul_rn(w1i, cv1.x));
    float cr3 = __fadd_rn(__fmul_rn(w2r, cv2.x), __fmul_rn(w2i, cv2.y));
    float ci3 = __fsub_rn(__fmul_rn(w2r, cv2.y), __fmul_rn(w2i, cv2.x));
    float cr4 = __fadd_rn(__fmul_rn(w3r, cv3.x), __fmul_rn(w3i, cv3.y));
    float ci4 = __fsub_rn(__fmul_rn(w3r, cv3.y), __fmul_rn(w3i, cv3.x));
    float tr1 = cr4 + cr2, tr4 = cr4 - cr2;
    float ti1 = ci2 + ci4, ti4 = ci2 - ci4;
    float tr2 = c0v.x + cr3, tr3 = c0v.x - cr3;
    float ti2 = c0v.y + ci3, ti3 = c0v.y - ci3;
    R4C r;
    r.o0 = make_float2(tr1 + tr2, ti1 + ti2);
    r.o3 = make_float2(tr2 - tr1, ti1 - ti2);
    r.o2 = make_float2(ti4 + tr3, tr4 + ti3);
    r.o1 = make_float2(tr3 - ti4, tr4 - ti3);
    return r;
}

// ---- generic radf4 middle pass (pass 3: B(P1) -> A(P2)) ----
template<int PIN, int POUT>
__device__ __forceinline__ void radf4_pass(
    const float* __restrict__ cc, float* __restrict__ ch,
    const float2* __restrict__ tw, int ido, int l1, int m_step, int t)
{
#define RD1(i)    cc[FDX(PIN, (i) + 1)]
#define RD2(L)    (*(const float2*)&cc[FDX(PIN, (L) + 1)])
#define WR1(i, v) do { ch[FDX(POUT, (i) + 1)] = (v); } while (0)
#define WR2(L, v) do { *(float2*)&ch[FDX(POUT, (L) + 1)] = (v); } while (0)
    if (t < l1) {
        int k = t;
        float4 r = r4_real(RD1(ido * k), RD1(ido * (k + l1)),
                           RD1(ido * (k + 2 * l1)), RD1(ido * (k + 3 * l1)));
        WR1(ido * (4 * k),               r.x);
        WR1((ido - 1) + ido * (1 + 4*k), r.y);
        WR1(ido * (2 + 4 * k),           r.z);
        WR1((ido - 1) + ido * (3 + 4*k), r.w);
    }
    const int nI = (ido >> 1) - 1;
    const int s2 = l1, e2 = l1 + l1 * nI;
    if (t >= s2 && t < e2) {
        int q = t - s2;
        int k = q % l1, ii = q / l1;
        int i = 2 + 2 * ii;
        int ic = ido - i;
        int m1 = (i >> 1) * m_step;
        R4C r = r4_cplx(RD2((i-1) + ido*k),
                        RD2((i-1) + ido*(k + l1)),
                        RD2((i-1) + ido*(k + 2*l1)),
                        RD2((i-1) + ido*(k + 3*l1)),
                        tw[m1], tw[2*m1], tw[3*m1]);
        WR2((i-1)  + ido*(4*k),     r.o0);
        WR2((ic-1) + ido*(3 + 4*k), r.o3);
        WR2((i-1)  + ido*(2 + 4*k), r.o2);
        WR2((ic-1) + ido*(1 + 4*k), r.o1);
    }
    if (t >= e2 && t < e2 + l1) {
        int k = t - e2;
        float4 r = r4_tail(RD1((ido-1) + ido*k), RD1((ido-1) + ido*(k + l1)),
                           RD1((ido-1) + ido*(k + 2*l1)), RD1((ido-1) + ido*(k + 3*l1)));
        WR1((ido-1) + ido*(4*k),     r.x);
        WR1(ido*(1 + 4*k),           r.y);
        WR1((ido-1) + ido*(2 + 4*k), r.z);
        WR1(ido*(3 + 4*k),           r.w);
    }
#undef RD1
#undef RD2
#undef WR1
#undef WR2
}

__global__ __launch_bounds__(TPB, 7) void spectral_kernel(
    const float* __restrict__ x, const float* __restrict__ gains,
    const float* __restrict__ bias, float* __restrict__ y, int kk)
{
    __shared__ __align__(16) float s_pool[3212];
    __shared__ float2 s_tw[RR];
    __shared__ float  s_sc[RR];
    __shared__ float  s_g[KMAX];
    __shared__ int    s_hist[256];
    __shared__ int    s_goff[256];
    __shared__ unsigned long long s_ckey[CKMAX];
    __shared__ int    s_wsumi[8];
    __shared__ float  s_wmax[8];
    __shared__ int    s_cut;

    float* B = s_pool;
    float* A = s_pool + BSTRIDE;
    float* H = s_pool + 2 * BSTRIDE;

    const int t = threadIdx.x;
    const int lane = t & 31;
    const int wrp = t >> 5;
    const long long row = blockIdx.x;
    const float* xrow = x + row * DD;

    // ---- fused pass 1+2 (threads 0..63) overlapped with s_tw/s_g staging ----
    if (t < 64) {
        const int k2 = t;
        float q[4][4];
#pragma unroll
        for (int m = 0; m < 4; ++m) {
            int base = k2 + 64 * m;
            float4 r = r4_real(xrow[base], xrow[base + 256],
                               xrow[base + 512], xrow[base + 768]);
            q[m][0] = r.x; q[m][1] = r.y; q[m][2] = r.z; q[m][3] = r.w;
        }
#define WB1(j, v) B[FDX(1, 16*k2 + (j) + 1)] = (v)
#define WB2(j, v) *(float2*)&B[FDX(1, 16*k2 + (j) + 1)] = (v)
        {   float4 r = r4_real(q[0][0], q[1][0], q[2][0], q[3][0]);
            WB1(0, r.x); WB2(7, make_float2(r.y, r.z)); WB1(15, r.w);
        }
        {   float4 r = r4_tail(q[0][3], q[1][3], q[2][3], q[3][3]);
            WB2(3, make_float2(r.x, r.y)); WB2(11, make_float2(r.z, r.w));
        }
        {   float2 w1 = g_tw[64], w2 = g_tw[128], w3 = g_tw[192];
            R4C r = r4_cplx(make_float2(q[0][1], q[0][2]),
                            make_float2(q[1][1], q[1][2]),
                            make_float2(q[2][1], q[2][2]),
                            make_float2(q[3][1], q[3][2]),
                            w1, w2, w3);
            WB2(1, r.o0); WB2(5, r.o1); WB2(9, r.o2); WB2(13, r.o3);
        }
#undef WB1
#undef WB2
    } else {
        for (int i = t - 64; i < RR; i += 192) s_tw[i] = g_tw[i];
        for (int i = t - 64; i < kk; i += 192) s_g[i] = gains[i];
    }
    __syncthreads();

    // ---- pass 3 : B(P1) -> A(P2), ido=16, l1=16 ----
    radf4_pass<1,2>(B, A, s_tw, 16, 16, 16, t);
    __syncthreads();

    // ---- fused pass 4+5 : A(P2) -> H; idle threads init selection arrays ----
#define RD1A(i) A[FDX(2, (i) + 1)]
#define RD2A(L) (*(const float2*)&A[FDX(2, (L) + 1)])
    if (t < 62) {
        const int p = (t >> 1) + 1;
        const int h = t & 1;
        const int i4 = 2 * p;
        float2 ra[4], rb[4];
        {
            float2 w1 = s_tw[4*p], w2 = s_tw[8*p], w3 = s_tw[12*p];
#pragma unroll
            for (int k4 = 0; k4 < 4; ++k4) {
                R4C r = r4_cplx(RD2A((i4-1) + 64*k4),
                                RD2A((i4-1) + 64*(k4+4)),
                                RD2A((i4-1) + 64*(k4+8)),
                                RD2A((i4-1) + 64*(k4+12)),
                                w1, w2, w3);
                ra[k4] = h ? r.o1 : r.o0;
                rb[k4] = h ? r.o3 : r.o2;
            }
        }
        const int I5a = h ? (128 - i4) : i4;
        const int I5b = h ? (256 - i4) : (i4 + 128);
        float2 wa1 = s_tw[h ? (64 - p)      : p];
        float2 wa2 = s_tw[h ? (128 - 2*p)   : 2*p];
        float2 wa3 = s_tw[h ? (192 - 3*p)   : 3*p];
        float2 wb1 = s_tw[h ? (128 - p)     : (64 + p)];
        float2 wb2 = s_tw[h ? (256 - 2*p)   : (128 + 2*p)];
        float2 wb3 = s_tw[h ? (384 - 3*p)   : (192 + 3*p)];
#define EMIT5(I5, V, W1, W2, W3) do { \
            R4C r = r4_cplx((V)[0], (V)[1], (V)[2], (V)[3], (W1), (W2), (W3)); \
            *(float2*)&H[(I5)]        = r.o0; \
            *(float2*)&H[1024 - (I5)] = r.o3; \
            *(float2*)&H[(I5) + 512]  = r.o2; \
            *(float2*)&H[512 - (I5)]  = r.o1; \
        } while (0)
        EMIT5(I5a, ra, wa1, wa2, wa3);
        EMIT5(I5b, rb, wb1, wb2, wb3);
#undef EMIT5
    } else if (t == 64) {
        float q0[4][4];
#pragma unroll
        for (int k4 = 0; k4 < 4; ++k4) {
            float4 r = r4_real(RD1A(64*k4), RD1A(64*(k4+4)),
                               RD1A(64*(k4+8)), RD1A(64*(k4+12)));
            q0[k4][0] = r.x; q0[k4][1] = r.y; q0[k4][2] = r.z; q0[k4][3] = r.w;
        }
        {   float4 s = r4_real(q0[0][0], q0[1][0], q0[2][0], q0[3][0]);
            H[1] = s.x; H[512] = s.y; H[513] = s.z; H[1024] = s.w; }
        {   R4C r = r4_cplx(make_float2(q0[0][1], q0[0][2]),
                            make_float2(q0[1][1], q0[1][2]),
                            make_float2(q0[2][1], q0[2][2]),
                            make_float2(q0[3][1], q0[3][2]),
                            s_tw[64], s_tw[128], s_tw[192]);
            *(float2*)&H[128] = r.o0; *(float2*)&H[896] = r.o3;
            *(float2*)&H[640] = r.o2; *(float2*)&H[384] = r.o1; }
        {   float4 s = r4_tail(q0[0][3], q0[1][3], q0[2][3], q0[3][3]);
            *(float2*)&H[256] = make_float2(s.x, s.y);
            *(float2*)&H[768] = make_float2(s.z, s.w); }
    } else if (t == 96) {
        float qt[4][4];
#pragma unroll
        for (int k4 = 0; k4 < 4; ++k4) {
            float4 r = r4_tail(RD1A(63 + 64*k4), RD1A(63 + 64*(k4+4)),
                               RD1A(63 + 64*(k4+8)), RD1A(63 + 64*(k4+12)));
            qt[k4][0] = r.x; qt[k4][1] = r.y; qt[k4][2] = r.z; qt[k4][3] = r.w;
        }
        {   R4C r = r4_cplx(make_float2(qt[0][0], qt[0][1]),
                            make_float2(qt[1][0], qt[1][1]),
                            make_float2(qt[2][0], qt[2][1]),
                            make_float2(qt[3][0], qt[3][1]),
                            s_tw[32], s_tw[64], s_tw[96]);
            *(float2*)&H[64]  = r.o0; *(float2*)&H[960] = r.o3;
            *(float2*)&H[576] = r.o2; *(float2*)&H[448] = r.o1; }
        {   R4C r = r4_cplx(make_float2(qt[0][2], qt[0][3]),
                            make_float2(qt[1][2], qt[1][3]),
                            make_float2(qt[2][2], qt[2][3]),
                            make_float2(qt[3][2], qt[3][3]),
                            s_tw[96], s_tw[192], s_tw[288]);
            *(float2*)&H[192] = r.o0; *(float2*)&H[832] = r.o3;
            *(float2*)&H[704] = r.o2; *(float2*)&H[320] = r.o1; }
    } else if (t >= 128) {
        int u = t - 128;
        s_hist[u] = 0; s_goff[u] = 0;
        s_hist[u + 128] = 0; s_goff[u + 128] = 0;
        for (int i = u; i < RR; i += 128) s_sc[i] = 0.f;
    }
#undef RD1A
#undef RD2A
    __syncthreads();
    // H (shift 1): X0 = H[1]; Xk = (H[2k], H[2k+1]) k=1..511; X512 = H[1024]

    // ---- magnitudes in registers (XLA EmitHypot) + max reduce; v0,v1 kept for pack ----
    float2 v0, v1;
    float m0, m1, m2 = 0.f;
    {
        const float2* h2 = (const float2*)H;
        v0 = (t == 0) ? make_float2(H[1], 0.f) : h2[t];
        v1 = h2[t + 256];
        m0 = xla_hypot(v0.x, v0.y);
        m1 = xla_hypot(v1.x, v1.y);
        if (t == 0) m2 = xla_hypot(H[1024], 0.f);
    }
    float mv = fmaxf(m0, m1);
    if (t == 0) mv = fmaxf(mv, m2);
#pragma unroll
    for (int o = 16; o; o >>= 1) mv = fmaxf(mv, __shfl_xor_sync(0xffffffffu, mv, o));
    if (lane == 0) s_wmax[wrp] = mv;
    __syncthreads();
    if (t == 0) {
        float mz = s_wmax[0];
#pragma unroll
        for (int i2 = 1; i2 < 8; ++i2) mz = fmaxf(mz, s_wmax[i2]);
        s_wmax[0] = mz * 1.0000002f + 1e-30f;
    }
    __syncthreads();

    const float hi = s_wmax[0];
    const float inv = 256.f / hi;
    const int b0 = min((int)(m0 * inv), 255);
    const int b1 = min((int)(m1 * inv), 255);
    int b2 = 0;

    // ---- histogram from registers ----
    atomicAdd(&s_hist[b0], 1);
    atomicAdd(&s_hist[b1], 1);
    if (t == 0) { b2 = min((int)(m2 * inv), 255); atomicAdd(&s_hist[b2], 1); }
    __syncthreads();

    // ---- suffix scan ----
    {
        int v = s_hist[t];
#pragma unroll
        for (int d = 1; d < 32; d <<= 1) {
            int tmp = __shfl_down_sync(0xffffffffu, v, d);
            if (lane + d < 32) v += tmp;
        }
        if (lane == 0) s_wsumi[wrp] = v;
        __syncthreads();
        int add = 0;
#pragma unroll
        for (int w = 0; w < 8; ++w) add += (w > wrp) ? s_wsumi[w] : 0;
        v += add;
        s_hist[t] = v;
    }
    __syncthreads();

    // ---- cut bin ----
    {
        int sa = s_hist[t];
        int sb = (t == 255) ? 0 : s_hist[t + 1];
        if (sa >= kk && sb < kk) s_cut = t;
    }
    __syncthreads();
    const int cutb = s_cut;
    const int cnt = s_hist[cutb];

    // ---- compact candidates from registers ----
    if (b0 >= cutb) {
        int gs = (b0 < 255) ? s_hist[b0 + 1] : 0;
        int off = atomicAdd(&s_goff[b0], 1);
        s_ckey[gs + off] = (((unsigned long long)__float_as_uint(m0)) << 10)
                         | (unsigned long long)(1023 - t);
    }
    if (b1 >= cutb) {
        int gs = (b1 < 255) ? s_hist[b1 + 1] : 0;
        int off = atomicAdd(&s_goff[b1], 1);
        s_ckey[gs + off] = (((unsigned long long)__float_as_uint(m1)) << 10)
                         | (unsigned long long)(1023 - (t + 256));
    }
    if (t == 0 && b2 >= cutb) {
        int gs = (b2 < 255) ? s_hist[b2 + 1] : 0;
        int off = atomicAdd(&s_goff[b2], 1);
        s_ckey[gs + off] = (((unsigned long long)__float_as_uint(m2)) << 10)
                         | (unsigned long long)(1023 - 512);
    }
    __syncthreads();

    // ---- exact rank within bin; scatter gains ----
    for (int i = t; i < cnt; i += TPB) {
        unsigned long long ki = s_ckey[i];
        float m = __uint_as_float((unsigned)(ki >> 10));
        int b = min((int)(m * inv), 255);
        int gs = (b < 255) ? s_hist[b + 1] : 0;
        int ge = gs + s_goff[b];
        int r  = gs;
        for (int j = gs; j < ge; ++j) r += (s_ckey[j] > ki) ? 1 : 0;
        if (r < kk) {
            int f = 1023 - (int)(ki & 1023ull);
            s_sc[f] = s_g[r];
        }
    }
    __syncthreads();

    // ---- pack (Yk from registers v0/v1, only mirrors read) + fused stage 1 ----
    float2* zb = (float2*)s_pool;
    {
        const float2* h2 = (const float2*)H;
        const float sc1 = 1.f / 1024.f;
        float2 st[2];
        {   // h=0: k=t, km=512-t
            float2 Yk = v0;
            float2 Ym = (t == 0) ? make_float2(H[1024], 0.f) : h2[512 - t];
            float a1 = s_sc[t];       Yk.x *= a1; Yk.y *= a1;
            float a2 = s_sc[512 - t]; Ym.x *= a2; Ym.y *= a2;
            float px = Yk.x + Ym.x, py = Yk.y - Ym.y;
            float qx = Yk.x - Ym.x, qy = Yk.y + Ym.y;
            float2 w = s_tw[t];
            float tx = qx * w.x + qy * w.y;
            float ty = qy * w.x - qx * w.y;
            st[0] = make_float2(sc1 * (px - ty), sc1 * (py + tx));
        }
        {   // h=1: k=t+256, km=256-t
            float2 Yk = v1;
            float2 Ym = h2[256 - t];      // t=0 -> h2[256], correct
            float a1 = s_sc[t + 256]; Yk.x *= a1; Yk.y *= a1;
            float a2 = s_sc[256 - t]; Ym.x *= a2; Ym.y *= a2;
            float px = Yk.x + Ym.x, py = Yk.y - Ym.y;
            float qx = Yk.x - Ym.x, qy = Yk.y + Ym.y;
            float2 w = s_tw[t + 256];
            float tx = qx * w.x + qy * w.y;
            float ty = qy * w.x - qx * w.y;
            st[1] = make_float2(sc1 * (px - ty), sc1 * (py + tx));
        }
        int br = __brev(t) >> 23;   // even for t<256; stage-1 pair (br, br+1)
        zb[PIDX(br)]     = make_float2(st[0].x + st[1].x, st[0].y + st[1].y);
        zb[PIDX(br + 1)] = make_float2(st[0].x - st[1].x, st[0].y - st[1].y);
    }
    __syncthreads();

    // ---- inverse: fused double radix-2 stages (2,3)(4,5)(6,7) ----
#pragma unroll
    for (int lsp = 2; lsp <= 6; lsp += 2) {
        if (t < 128) {
            const int h1 = 1 << (lsp - 1);
            const int low = t & (h1 - 1);
            const int high = t >> (lsp - 1);
            const int bidx = low | (high << (lsp + 1));
            float2 z0 = zb[PIDX(bidx)];
            float2 z1 = zb[PIDX(bidx + h1)];
            float2 z2 = zb[PIDX(bidx + 2 * h1)];
            float2 z3 = zb[PIDX(bidx + 3 * h1)];
            float2 wa = s_tw[low << (10 - lsp)];
            int wbi = low << (9 - lsp);
            float2 wb = s_tw[wbi];
            float2 wc = s_tw[wbi + 256];
            float2 t1 = cmulc(z1, wa);
            float2 a0 = make_float2(z0.x + t1.x, z0.y + t1.y);
            float2 a1 = make_float2(z0.x - t1.x, z0.y - t1.y);
            float2 t2 = cmulc(z3, wa);
            float2 a2 = make_float2(z2.x + t2.x, z2.y + t2.y);
            float2 a3 = make_float2(z2.x - t2.x, z2.y - t2.y);
            float2 u = cmulc(a2, wb);
            float2 v = cmulc(a3, wc);
            zb[PIDX(bidx)]          = make_float2(a0.x + u.x, a0.y + u.y);
            zb[PIDX(bidx + h1)]     = make_float2(a1.x + v.x, a1.y + v.y);
            zb[PIDX(bidx + 2*h1)]   = make_float2(a0.x - u.x, a0.y - u.y);
            zb[PIDX(bidx + 3*h1)]   = make_float2(a1.x - v.x, a1.y - v.y);
        }
        __syncthreads();
    }

    // ---- fused stages 8+9 + bias add + gmem write (threads 0..127, 4 outputs) ----
    if (t < 128) {
        const float2* b2 = (const float2*)bias;
        float2* yr = (float2*)(y + row * DD);
        float2 u0 = zb[PIDX(t)];
        float2 u1 = zb[PIDX(t + 128)];
        float2 u2 = zb[PIDX(t + 256)];
        float2 u3 = zb[PIDX(t + 384)];
        float2 w8 = s_tw[t << 2];
        float2 t1 = cmulc(u1, w8);
        float2 a0 = make_float2(u0.x + t1.x, u0.y + t1.y);
        float2 a1 = make_float2(u0.x - t1.x, u0.y - t1.y);
        float2 t2 = cmulc(u3, w8);
        float2 a2 = make_float2(u2.x + t2.x, u2.y + t2.y);
        float2 a3 = make_float2(u2.x - t2.x, u2.y - t2.y);
        float2 w9a = s_tw[t << 1];
        float2 w9b = s_tw[(t << 1) + 256];
        float2 vv0 = cmulc(a2, w9a);
        float2 vv1 = cmulc(a3, w9b);
        float2 bb0 = b2[t];
        float2 bb1 = b2[t + 128];
        float2 bb2 = b2[t + 256];
        float2 bb3 = b2[t + 384];
        yr[t]       = make_float2(a0.x + vv0.x + bb0.x, a0.y + vv0.y + bb0.y);
        yr[t + 128] = make_float2(a1.x + vv1.x + bb1.x, a1.y + vv1.y + bb1.y);
        yr[t + 256] = make_float2(a0.x - vv0.x + bb2.x, a0.y - vv0.y + bb2.y);
        yr[t + 384] = make_float2(a1.x - vv1.x + bb3.x, a1.y - vv1.y + bb3.y);
    }
}

extern "C" void kernel_launch(void* const* d_in, const int* in_sizes, int n_in,
                              void* d_out, int out_size) {
    const float* x     = (const float*)d_in[0];
    const float* gains = (const float*)d_in[1];
    const float* bias  = (const float*)d_in[2];
    float* y = (float*)d_out;

    int rows = in_sizes[0] / DD;
    int kk = in_sizes[1];
    if (kk > KMAX) kk = KMAX;

    tw_init_kernel<<<3, 256>>>();
    spectral_kernel<<<rows, TPB>>>(x, gains, bias, y, kk);
}